// round 13
// baseline (speedup 1.0000x reference)
#include <cuda_runtime.h>
#include <cuda_bf16.h>
#include <cstdint>

#define NB 8192
#define ND 512
#define NK 2048
#define NL 4
#define EPSN 1e-5f
#define TEMP_MIN 0.01f

#define BM 128
#define BN 128

// Scratch (static device arrays; no allocations)
static __device__ float g_y[NB * ND];
static __device__ __align__(16) __nv_bfloat16 g_fh[NB * ND];
static __device__ __align__(16) __nv_bfloat16 g_fl[NB * ND];
static __device__ __align__(16) __nv_bfloat16 g_wh[ND * ND];
static __device__ __align__(16) __nv_bfloat16 g_wl[ND * ND];
static __device__ __align__(16) __nv_bfloat16 g_xh[NB * ND];
static __device__ __align__(16) __nv_bfloat16 g_ch[NK * ND];
static __device__ float g_rn[NB];
static __device__ float g_cn[NL * NK];

// ---------------------------------------------------------------------------
__device__ __forceinline__ uint32_t smem_u32(const void* p) {
    uint32_t a;
    asm("{ .reg .u64 t; cvta.to.shared.u64 t, %1; cvt.u32.u64 %0, t; }" : "=r"(a) : "l"(p));
    return a;
}

#define CPA(dst, src) \
    asm volatile("cp.async.cg.shared.global [%0], [%1], 16;" :: "r"(dst), "l"(src) : "memory")
#define CPA_COMMIT() asm volatile("cp.async.commit_group;" ::: "memory")
#define CPA_WAIT(N)  asm volatile("cp.async.wait_group %0;" :: "n"(N) : "memory")

__device__ __forceinline__ void cpa_wait_dyn(int n) {
    switch (n) {
        case 0: CPA_WAIT(0); break;
        case 1: CPA_WAIT(1); break;
        case 2: CPA_WAIT(2); break;
        case 3: CPA_WAIT(3); break;
        default: CPA_WAIT(4); break;
    }
}

__device__ __forceinline__ void ldm_x4(uint32_t* r, uint32_t addr) {
    asm volatile("ldmatrix.sync.aligned.m8n8.x4.shared.b16 {%0,%1,%2,%3}, [%4];"
                 : "=r"(r[0]), "=r"(r[1]), "=r"(r[2]), "=r"(r[3]) : "r"(addr));
}

__device__ __forceinline__ void mma16816(float* c, const uint32_t* a, const uint32_t* b) {
    asm volatile(
        "mma.sync.aligned.m16n8k16.row.col.f32.bf16.bf16.f32 "
        "{%0,%1,%2,%3}, {%4,%5,%6,%7}, {%8,%9}, {%0,%1,%2,%3};"
        : "+f"(c[0]), "+f"(c[1]), "+f"(c[2]), "+f"(c[3])
        : "r"(a[0]), "r"(a[1]), "r"(a[2]), "r"(a[3]), "r"(b[0]), "r"(b[1]));
}

__device__ __forceinline__ void cvt4(float4 v, uint2& h, uint2& l) {
    __nv_bfloat162 h0 = __floats2bfloat162_rn(v.x, v.y);
    __nv_bfloat162 h1 = __floats2bfloat162_rn(v.z, v.w);
    float lx = v.x - __bfloat162float(h0.x);
    float ly = v.y - __bfloat162float(h0.y);
    float lz = v.z - __bfloat162float(h1.x);
    float lw = v.w - __bfloat162float(h1.y);
    __nv_bfloat162 l0 = __floats2bfloat162_rn(lx, ly);
    __nv_bfloat162 l1 = __floats2bfloat162_rn(lz, lw);
    h.x = *(uint32_t*)&h0; h.y = *(uint32_t*)&h1;
    l.x = *(uint32_t*)&l0; l.y = *(uint32_t*)&l1;
}

// BK=32 layout: 64B rows, 4 x 16B chunks, 2-row-group XOR swizzle
__device__ __forceinline__ uint32_t swz32(int row, int cc) {
    return (uint32_t)(row * 64 + ((cc ^ ((row >> 1) & 3)) << 4));
}
// BK=64 layout: 128B rows, 8 x 16B chunks, full SW128 row swizzle
__device__ __forceinline__ uint32_t swz64(int row, int cc) {
    return (uint32_t)(row * 128 + ((cc ^ (row & 7)) << 4));
}

// ---------------------------------------------------------------------------
// Split/plain-bf16 tensor GEMM, cp.async pipeline, 2 CTAs/SM.
// MODE 0 (proj): 3-pass split-bf16, BK=32, DEPTH=3, +bias.
// MODE 1 (dist): 1-pass plain bf16, BK=64, DEPTH=3,
//                logits epilogue + fill spread across k16 steps.
// ---------------------------------------------------------------------------
template <int MODE, int DEPTH>
__global__ void __launch_bounds__(256, 2) gemm_mma(
    const __nv_bfloat16* __restrict__ Ah_g, const __nv_bfloat16* __restrict__ Al_g,
    const __nv_bfloat16* __restrict__ Bh_g, const __nv_bfloat16* __restrict__ Bl_g,
    float* __restrict__ C, int ldc,
    const float* __restrict__ bias, const float* __restrict__ rn,
    const float* __restrict__ cn, const float* __restrict__ scales,
    const float* __restrict__ temp) {
    constexpr int STAGE_B = 32768;                    // both modes: 32 KB/stage
    constexpr int NCH = (MODE == 0) ? 16 : 8;         // k-chunks
    constexpr int KSTEPS = (MODE == 0) ? 2 : 4;       // k16 steps per chunk
    constexpr uint32_t OFF_B = 16384;
    extern __shared__ char sm_[];
    const int tid = threadIdx.x;
    const int wid = tid >> 5, lane = tid & 31;
    const int bm = blockIdx.y * BM, bn = blockIdx.x * BN;
    const int wm = (wid & 1) * 64;
    const int wn = (wid >> 1) * 32;
    const uint32_t sbase = smem_u32(sm_);

    // staging coords
    const int r0 = tid >> 2, c0 = tid & 3;
    const uint32_t d32 = swz32(r0, c0);
    const uint32_t dA0 = swz64(r0, c0), dA1 = swz64(r0, c0 + 4);
    const uint32_t dA2 = swz64(r0 + 64, c0), dA3 = swz64(r0 + 64, c0 + 4);

    const char* pAh = (const char*)Ah_g + (size_t)(bm + r0) * 1024 + c0 * 16;
    const char* pAl = (MODE == 0) ? (const char*)Al_g + (size_t)(bm + r0) * 1024 + c0 * 16
                                  : nullptr;
    const char* pBh = (const char*)Bh_g + (size_t)(bn + r0) * 1024 + c0 * 16;
    const char* pBl = (MODE == 0) ? (const char*)Bl_g + (size_t)(bn + r0) * 1024 + c0 * 16
                                  : nullptr;

    float acc[4][4][4];
#pragma unroll
    for (int mi = 0; mi < 4; mi++)
#pragma unroll
        for (int ni = 0; ni < 4; ni++)
#pragma unroll
            for (int j = 0; j < 4; j++) acc[mi][ni][j] = 0.f;

    const int arow = lane & 15, asel = lane >> 4;
    const int brow = ((lane >> 4) << 3) + (lane & 7);
    const int bsel = (lane >> 3) & 1;

    auto issue_stage = [&](uint32_t sb, int koff) {
        if (MODE == 0) {
            CPA(sb + d32,                pAh + koff);
            CPA(sb + d32 + 4096,         pAh + koff + 65536);
            CPA(sb + 8192 + d32,         pAl + koff);
            CPA(sb + 8192 + d32 + 4096,  pAl + koff + 65536);
            CPA(sb + 16384 + d32,        pBh + koff);
            CPA(sb + 16384 + d32 + 4096, pBh + koff + 65536);
            CPA(sb + 24576 + d32,        pBl + koff);
            CPA(sb + 24576 + d32 + 4096, pBl + koff + 65536);
        } else {
            CPA(sb + dA0,         pAh + koff);
            CPA(sb + dA1,         pAh + koff + 64);
            CPA(sb + dA2,         pAh + koff + 65536);
            CPA(sb + dA3,         pAh + koff + 65536 + 64);
            CPA(sb + 16384 + dA0, pBh + koff);
            CPA(sb + 16384 + dA1, pBh + koff + 64);
            CPA(sb + 16384 + dA2, pBh + koff + 65536);
            CPA(sb + 16384 + dA3, pBh + koff + 65536 + 64);
        }
        CPA_COMMIT();
    };

    constexpr int KBYTES = (MODE == 0) ? 64 : 128;
#pragma unroll
    for (int g = 0; g < DEPTH - 1; g++) issue_stage(sbase + g * STAGE_B, g * KBYTES);

    // Precompute fill values (dist only)
    float s0 = 0.f, invt = 0.f;
    float* sval = (float*)(sm_ + DEPTH * STAGE_B);
    if (MODE == 1) {
        s0 = scales[0];
        invt = 1.0f / fmaxf(temp[0], TEMP_MIN);
        int cbase = NK + blockIdx.x * 384;
        for (int i = tid; i < 384; i += 256) sval[i] = -cn[cbase + i] * invt;
    }
    const int fbase = (MODE == 1) ? NK + blockIdx.x * 384 : 0;

#pragma unroll 1
    for (int kc = 0; kc < NCH; kc++) {
        if (kc + DEPTH - 1 < NCH) {
            CPA_WAIT(DEPTH - 2);
            __syncthreads();
            issue_stage(sbase + ((kc + DEPTH - 1) % DEPTH) * STAGE_B, (kc + DEPTH - 1) * KBYTES);
        } else {
            int rem = NCH - 1 - kc;
            cpa_wait_dyn(rem < DEPTH - 2 ? rem : DEPTH - 2);
            __syncthreads();
        }
        const uint32_t ah = sbase + (kc % DEPTH) * STAGE_B;
        const uint32_t al = ah + 8192;
        const uint32_t bh = ah + OFF_B;
        const uint32_t bl = ah + 24576;

#pragma unroll
        for (int ks = 0; ks < KSTEPS; ks++) {
            // Fill stores spread across ksteps (dist: 2,2,1,1 per chunk)
            if (MODE == 1) {
                const int nst = (ks < 2) ? 2 : 1;
#pragma unroll
                for (int q = 0; q < nst; q++) {
                    int jj = (ks < 2) ? ks * 2 + q : 4 + (ks - 2);
                    int idx = tid + (kc * 6 + jj) * 256;  // < 12288
                    int row = idx / 96;
                    int cc = (idx - row * 96) * 4;
                    float4 v = *(float4*)&sval[cc];
                    __stcs((float4*)&C[(size_t)(bm + row) * ldc + fbase + cc], v);
                }
            }

            const int ccA = ks * 2 + asel;
            const int ccB = ks * 2 + bsel;
            uint32_t bfh[4][2], bfl[4][2];
            {
                int rb = wn + brow;
                uint32_t o1, o2;
                if (MODE == 0) { o1 = swz32(rb, ccB); o2 = swz32(rb + 16, ccB); }
                else           { o1 = swz64(rb, ccB); o2 = swz64(rb + 16, ccB); }
                uint32_t t4[4];
                ldm_x4(t4, bh + o1);
                bfh[0][0] = t4[0]; bfh[0][1] = t4[1]; bfh[1][0] = t4[2]; bfh[1][1] = t4[3];
                ldm_x4(t4, bh + o2);
                bfh[2][0] = t4[0]; bfh[2][1] = t4[1]; bfh[3][0] = t4[2]; bfh[3][1] = t4[3];
                if (MODE == 0) {
                    ldm_x4(t4, bl + o1);
                    bfl[0][0] = t4[0]; bfl[0][1] = t4[1]; bfl[1][0] = t4[2]; bfl[1][1] = t4[3];
                    ldm_x4(t4, bl + o2);
                    bfl[2][0] = t4[0]; bfl[2][1] = t4[1]; bfl[3][0] = t4[2]; bfl[3][1] = t4[3];
                }
            }
#pragma unroll
            for (int mi = 0; mi < 4; mi++) {
                int ra = wm + mi * 16 + arow;
                uint32_t ao = (MODE == 0) ? swz32(ra, ccA) : swz64(ra, ccA);
                uint32_t afh[4];
                ldm_x4(afh, ah + ao);
#pragma unroll
                for (int ni = 0; ni < 4; ni++) mma16816(acc[mi][ni], afh, bfh[ni]);
                if (MODE == 0) {
#pragma unroll
                    for (int ni = 0; ni < 4; ni++) mma16816(acc[mi][ni], afh, bfl[ni]);
                    uint32_t afl[4];
                    ldm_x4(afl, al + ao);
#pragma unroll
                    for (int ni = 0; ni < 4; ni++) mma16816(acc[mi][ni], afl, bfh[ni]);
                }
            }
        }
    }

    // Epilogue (logits / bias; fill already done in-loop)
    const int gid = lane >> 2, t4i = lane & 3;
#pragma unroll
    for (int mi = 0; mi < 4; mi++) {
        int r = bm + wm + mi * 16 + gid;
#pragma unroll
        for (int ni = 0; ni < 4; ni++) {
            int c = bn + wn + ni * 8 + t4i * 2;
            float* a4 = acc[mi][ni];
            if (MODE == 0) {
                float b0 = bias[c], b1 = bias[c + 1];
                *(float2*)&C[(size_t)r * ldc + c] = make_float2(a4[0] + b0, a4[1] + b1);
                *(float2*)&C[(size_t)(r + 8) * ldc + c] = make_float2(a4[2] + b0, a4[3] + b1);
            } else {
                float m2s = 2.0f * s0;
                float cv0 = cn[c], cv1 = cn[c + 1];
                float rv0 = rn[r], rv1 = rn[r + 8];
                float2 o0, o1;
                o0.x = -(rv0 + cv0 - m2s * a4[0]) * invt;
                o0.y = -(rv0 + cv1 - m2s * a4[1]) * invt;
                o1.x = -(rv1 + cv0 - m2s * a4[2]) * invt;
                o1.y = -(rv1 + cv1 - m2s * a4[3]) * invt;
                __stcs((float2*)&C[(size_t)r * ldc + c], o0);
                __stcs((float2*)&C[(size_t)(r + 8) * ldc + c], o1);
            }
        }
    }
}

// ---------------------------------------------------------------------------
__global__ void __launch_bounds__(256) conv_kernel(const float* __restrict__ src,
                                                   __nv_bfloat16* __restrict__ h,
                                                   __nv_bfloat16* __restrict__ l) {
    int idx = blockIdx.x * 256 + threadIdx.x;
    float4 v = ((const float4*)src)[idx];
    uint2 hh, ll;
    cvt4(v, hh, ll);
    ((uint2*)h)[idx] = hh;
    ((uint2*)l)[idx] = ll;
}

// ---------------------------------------------------------------------------
__global__ void __launch_bounds__(256) cbnorm_kernel(const float* __restrict__ cb,
                                                     float* __restrict__ cn) {
    int row = blockIdx.x * 8 + (threadIdx.x >> 5);
    int lane = threadIdx.x & 31;
    const float* p = cb + (size_t)row * ND;
    float s = 0.f;
#pragma unroll
    for (int i = 0; i < 4; i++) {
        int off = (lane + i * 32) * 4;
        float4 v = *(const float4*)&p[off];
        s += v.x * v.x + v.y * v.y + v.z * v.z + v.w * v.w;
        if (row < NK) {
            __nv_bfloat162 h0 = __floats2bfloat162_rn(v.x, v.y);
            __nv_bfloat162 h1 = __floats2bfloat162_rn(v.z, v.w);
            uint2 hh;
            hh.x = *(uint32_t*)&h0; hh.y = *(uint32_t*)&h1;
            *(uint2*)&g_ch[(size_t)row * ND + off] = hh;
        }
    }
#pragma unroll
    for (int o = 16; o > 0; o >>= 1) s += __shfl_xor_sync(0xffffffffu, s, o);
    if (lane == 0) cn[row] = s;
}

// ---------------------------------------------------------------------------
// Warp-per-2-rows fused LN(affine)+ReLU -> x hi bf16, LN2 (no affine), row norm.
// Two rows per warp doubles load-level parallelism (MLP 4 -> 8).
// ---------------------------------------------------------------------------
__global__ void __launch_bounds__(256) ln_kernel(const float* __restrict__ lng,
                                                 const float* __restrict__ lnb,
                                                 const float* __restrict__ scales,
                                                 float* __restrict__ q_out) {
    int warp = blockIdx.x * 8 + (threadIdx.x >> 5);
    int b0 = warp * 2, b1 = b0 + 1;
    int lane = threadIdx.x & 31;
    const float* y0 = g_y + (size_t)b0 * ND;
    const float* y1 = g_y + (size_t)b1 * ND;

    float4 v0[4], v1[4];
    float sA = 0.f, s2A = 0.f, sB = 0.f, s2B = 0.f;
#pragma unroll
    for (int i = 0; i < 4; i++) {
        v0[i] = *(const float4*)&y0[(lane + i * 32) * 4];
        v1[i] = *(const float4*)&y1[(lane + i * 32) * 4];
    }
#pragma unroll
    for (int i = 0; i < 4; i++) {
        sA += v0[i].x + v0[i].y + v0[i].z + v0[i].w;
        s2A += v0[i].x * v0[i].x + v0[i].y * v0[i].y + v0[i].z * v0[i].z + v0[i].w * v0[i].w;
        sB += v1[i].x + v1[i].y + v1[i].z + v1[i].w;
        s2B += v1[i].x * v1[i].x + v1[i].y * v1[i].y + v1[i].z * v1[i].z + v1[i].w * v1[i].w;
    }
#pragma unroll
    for (int o = 16; o > 0; o >>= 1) {
        sA += __shfl_xor_sync(0xffffffffu, sA, o);
        s2A += __shfl_xor_sync(0xffffffffu, s2A, o);
        sB += __shfl_xor_sync(0xffffffffu, sB, o);
        s2B += __shfl_xor_sync(0xffffffffu, s2B, o);
    }
    float muA = sA * (1.0f / ND);
    float rstdA = rsqrtf(s2A * (1.0f / ND) - muA * muA + EPSN);
    float muB = sB * (1.0f / ND);
    float rstdB = rsqrtf(s2B * (1.0f / ND) - muB * muB + EPSN);

    float x0[16], x1[16];
    float ssA = 0.f, ss2A = 0.f, ssB = 0.f, ss2B = 0.f;
    float s0 = scales[0];
#pragma unroll
    for (int i = 0; i < 4; i++) {
        int off = (lane + i * 32) * 4;
        float4 g = *(const float4*)&lng[off];
        float4 bb = *(const float4*)&lnb[off];
        const float* gi = &g.x;
        const float* bi = &bb.x;
        const float* viA = &v0[i].x;
        const float* viB = &v1[i].x;
#pragma unroll
        for (int j = 0; j < 4; j++) {
            float xa = fmaxf((viA[j] - muA) * rstdA * gi[j] + bi[j], 0.0f);
            float xb = fmaxf((viB[j] - muB) * rstdB * gi[j] + bi[j], 0.0f);
            x0[i * 4 + j] = xa;
            x1[i * 4 + j] = xb;
            float sa = s0 * xa, sb = s0 * xb;
            ssA += sa; ss2A += sa * sa;
            ssB += sb; ss2B += sb * sb;
        }
        __nv_bfloat162 hA0 = __floats2bfloat162_rn(x0[i * 4], x0[i * 4 + 1]);
        __nv_bfloat162 hA1 = __floats2bfloat162_rn(x0[i * 4 + 2], x0[i * 4 + 3]);
        __nv_bfloat162 hB0 = __floats2bfloat162_rn(x1[i * 4], x1[i * 4 + 1]);
        __nv_bfloat162 hB1 = __floats2bfloat162_rn(x1[i * 4 + 2], x1[i * 4 + 3]);
        uint2 ha, hb;
        ha.x = *(uint32_t*)&hA0; ha.y = *(uint32_t*)&hA1;
        hb.x = *(uint32_t*)&hB0; hb.y = *(uint32_t*)&hB1;
        *(uint2*)&g_xh[(size_t)b0 * ND + off] = ha;
        *(uint2*)&g_xh[(size_t)b1 * ND + off] = hb;
    }
#pragma unroll
    for (int o = 16; o > 0; o >>= 1) {
        ssA += __shfl_xor_sync(0xffffffffu, ssA, o);
        ss2A += __shfl_xor_sync(0xffffffffu, ss2A, o);
        ssB += __shfl_xor_sync(0xffffffffu, ssB, o);
        ss2B += __shfl_xor_sync(0xffffffffu, ss2B, o);
    }
    if (lane == 0) { g_rn[b0] = ss2A; g_rn[b1] = ss2B; }
    float mu2A = ssA * (1.0f / ND);
    float rstd2A = rsqrtf(ss2A * (1.0f / ND) - mu2A * mu2A + EPSN);
    float mu2B = ssB * (1.0f / ND);
    float rstd2B = rsqrtf(ss2B * (1.0f / ND) - mu2B * mu2B + EPSN);
#pragma unroll
    for (int i = 0; i < 4; i++) {
        int off = (lane + i * 32) * 4;
        float4 qa, qb;
        qa.x = (s0 * x0[i * 4 + 0] - mu2A) * rstd2A;
        qa.y = (s0 * x0[i * 4 + 1] - mu2A) * rstd2A;
        qa.z = (s0 * x0[i * 4 + 2] - mu2A) * rstd2A;
        qa.w = (s0 * x0[i * 4 + 3] - mu2A) * rstd2A;
        qb.x = (s0 * x1[i * 4 + 0] - mu2B) * rstd2B;
        qb.y = (s0 * x1[i * 4 + 1] - mu2B) * rstd2B;
        qb.z = (s0 * x1[i * 4 + 2] - mu2B) * rstd2B;
        qb.w = (s0 * x1[i * 4 + 3] - mu2B) * rstd2B;
        *(float4*)&q_out[(size_t)b0 * ND + off] = qa;
        *(float4*)&q_out[(size_t)b1 * ND + off] = qb;
    }
}

// ---------------------------------------------------------------------------
extern "C" void kernel_launch(void* const* d_in, const int* in_sizes, int n_in,
                              void* d_out, int out_size) {
    const float* features = (const float*)d_in[0];
    const float* Wp       = (const float*)d_in[1];
    const float* bproj    = (const float*)d_in[2];
    const float* lng      = (const float*)d_in[3];
    const float* lnb      = (const float*)d_in[4];
    const float* cbs      = (const float*)d_in[5];
    const float* scales   = (const float*)d_in[6];
    const float* temp     = (const float*)d_in[7];
    float* out = (float*)d_out;
    float* out_q = out + (size_t)NB * NL * NK;

    float *dy, *drn, *dcn;
    __nv_bfloat16 *dfh, *dfl, *dwh, *dwl, *dxh, *dch;
    cudaGetSymbolAddress((void**)&dy, g_y);
    cudaGetSymbolAddress((void**)&drn, g_rn);
    cudaGetSymbolAddress((void**)&dcn, g_cn);
    cudaGetSymbolAddress((void**)&dfh, g_fh);
    cudaGetSymbolAddress((void**)&dfl, g_fl);
    cudaGetSymbolAddress((void**)&dwh, g_wh);
    cudaGetSymbolAddress((void**)&dwl, g_wl);
    cudaGetSymbolAddress((void**)&dxh, g_xh);
    cudaGetSymbolAddress((void**)&dch, g_ch);

    const int SMEM_PROJ = 3 * 32768;
    const int SMEM_DIST = 3 * 32768 + 1536;
    cudaFuncSetAttribute((gemm_mma<0, 3>), cudaFuncAttributeMaxDynamicSharedMemorySize, SMEM_PROJ);
    cudaFuncSetAttribute((gemm_mma<1, 3>), cudaFuncAttributeMaxDynamicSharedMemorySize, SMEM_DIST);

    // 0. preconvert features and W_proj
    conv_kernel<<<NB * ND / 1024, 256>>>(features, dfh, dfl);
    conv_kernel<<<ND * ND / 1024, 256>>>(Wp, dwh, dwl);
    // 1. proj GEMM (3-pass split bf16, BK=32)
    {
        dim3 grid(ND / BN, NB / BM);
        gemm_mma<0, 3><<<grid, 256, SMEM_PROJ>>>(dfh, dfl, dwh, dwl, dy, ND, bproj,
                                                 nullptr, nullptr, nullptr, nullptr);
    }
    // 2. fused LN + ReLU + LN2 + rownorm (2 rows per warp)
    ln_kernel<<<NB / 16, 256>>>(lng, lnb, scales, out_q);
    // 3. codebook norms + codebook0 hi
    cbnorm_kernel<<<(NL * NK) / 8, 256>>>(cbs, dcn);
    // 4. dist GEMM (1-pass bf16, BK=64, DEPTH=3) + logits + in-kstep fill
    {
        dim3 grid(NK / BN, NB / BM);
        gemm_mma<1, 3><<<grid, 256, SMEM_DIST>>>(dxh, nullptr, dch, nullptr, out, NL * NK,
                                                 nullptr, drn, dcn, scales, temp);
    }
}

// round 15
// speedup vs baseline: 1.0247x; 1.0247x over previous
#include <cuda_runtime.h>
#include <cuda_bf16.h>
#include <cstdint>

#define NB 8192
#define ND 512
#define NK 2048
#define NL 4
#define EPSN 1e-5f
#define TEMP_MIN 0.01f

#define BM 128
#define BN 128

// Scratch (static device arrays; no allocations)
static __device__ float g_y[NB * ND];
static __device__ __align__(16) __nv_bfloat16 g_fh[NB * ND];
static __device__ __align__(16) __nv_bfloat16 g_fl[NB * ND];
static __device__ __align__(16) __nv_bfloat16 g_wh[ND * ND];
static __device__ __align__(16) __nv_bfloat16 g_wl[ND * ND];
static __device__ __align__(16) __nv_bfloat16 g_xh[NB * ND];
static __device__ __align__(16) __nv_bfloat16 g_ch[NK * ND];
static __device__ float g_rn[NB];
static __device__ float g_cn[NL * NK];

// ---------------------------------------------------------------------------
__device__ __forceinline__ uint32_t smem_u32(const void* p) {
    uint32_t a;
    asm("{ .reg .u64 t; cvta.to.shared.u64 t, %1; cvt.u32.u64 %0, t; }" : "=r"(a) : "l"(p));
    return a;
}

#define CPA(dst, src) \
    asm volatile("cp.async.cg.shared.global [%0], [%1], 16;" :: "r"(dst), "l"(src) : "memory")
#define CPA_COMMIT() asm volatile("cp.async.commit_group;" ::: "memory")
#define CPA_WAIT(N)  asm volatile("cp.async.wait_group %0;" :: "n"(N) : "memory")

__device__ __forceinline__ void cpa_wait_dyn(int n) {
    switch (n) {
        case 0: CPA_WAIT(0); break;
        case 1: CPA_WAIT(1); break;
        case 2: CPA_WAIT(2); break;
        case 3: CPA_WAIT(3); break;
        default: CPA_WAIT(4); break;
    }
}

__device__ __forceinline__ void ldm_x4(uint32_t* r, uint32_t addr) {
    asm volatile("ldmatrix.sync.aligned.m8n8.x4.shared.b16 {%0,%1,%2,%3}, [%4];"
                 : "=r"(r[0]), "=r"(r[1]), "=r"(r[2]), "=r"(r[3]) : "r"(addr));
}

__device__ __forceinline__ void mma16816(float* c, const uint32_t* a, const uint32_t* b) {
    asm volatile(
        "mma.sync.aligned.m16n8k16.row.col.f32.bf16.bf16.f32 "
        "{%0,%1,%2,%3}, {%4,%5,%6,%7}, {%8,%9}, {%0,%1,%2,%3};"
        : "+f"(c[0]), "+f"(c[1]), "+f"(c[2]), "+f"(c[3])
        : "r"(a[0]), "r"(a[1]), "r"(a[2]), "r"(a[3]), "r"(b[0]), "r"(b[1]));
}

__device__ __forceinline__ void cvt4(float4 v, uint2& h, uint2& l) {
    __nv_bfloat162 h0 = __floats2bfloat162_rn(v.x, v.y);
    __nv_bfloat162 h1 = __floats2bfloat162_rn(v.z, v.w);
    float lx = v.x - __bfloat162float(h0.x);
    float ly = v.y - __bfloat162float(h0.y);
    float lz = v.z - __bfloat162float(h1.x);
    float lw = v.w - __bfloat162float(h1.y);
    __nv_bfloat162 l0 = __floats2bfloat162_rn(lx, ly);
    __nv_bfloat162 l1 = __floats2bfloat162_rn(lz, lw);
    h.x = *(uint32_t*)&h0; h.y = *(uint32_t*)&h1;
    l.x = *(uint32_t*)&l0; l.y = *(uint32_t*)&l1;
}

// BK=32 layout: 64B rows, 4 x 16B chunks, 2-row-group XOR swizzle
__device__ __forceinline__ uint32_t swz32(int row, int cc) {
    return (uint32_t)(row * 64 + ((cc ^ ((row >> 1) & 3)) << 4));
}
// BK=64 layout: 128B rows, 8 x 16B chunks, full SW128 row swizzle
__device__ __forceinline__ uint32_t swz64(int row, int cc) {
    return (uint32_t)(row * 128 + ((cc ^ (row & 7)) << 4));
}

// ---------------------------------------------------------------------------
// Split/plain-bf16 tensor GEMM, cp.async pipeline, 2 CTAs/SM.
// MODE 0 (proj): 3-pass split-bf16, BK=32, DEPTH=3, +bias.
// MODE 1 (dist): 1-pass plain bf16, BK=64, DEPTH=3,
//                logits epilogue + interleaved levels-1..3 fill.
// ---------------------------------------------------------------------------
template <int MODE, int DEPTH>
__global__ void __launch_bounds__(256, 2) gemm_mma(
    const __nv_bfloat16* __restrict__ Ah_g, const __nv_bfloat16* __restrict__ Al_g,
    const __nv_bfloat16* __restrict__ Bh_g, const __nv_bfloat16* __restrict__ Bl_g,
    float* __restrict__ C, int ldc,
    const float* __restrict__ bias, const float* __restrict__ rn,
    const float* __restrict__ cn, const float* __restrict__ scales,
    const float* __restrict__ temp) {
    constexpr int STAGE_B = 32768;                    // both modes: 32 KB/stage
    constexpr int NCH = (MODE == 0) ? 16 : 8;         // k-chunks
    constexpr int KSTEPS = (MODE == 0) ? 2 : 4;       // k16 steps per chunk
    constexpr uint32_t OFF_B = 16384;
    extern __shared__ char sm_[];
    const int tid = threadIdx.x;
    const int wid = tid >> 5, lane = tid & 31;
    const int bm = blockIdx.y * BM, bn = blockIdx.x * BN;
    const int wm = (wid & 1) * 64;
    const int wn = (wid >> 1) * 32;
    const uint32_t sbase = smem_u32(sm_);

    // staging coords
    const int r0 = tid >> 2, c0 = tid & 3;
    const uint32_t d32 = swz32(r0, c0);
    const uint32_t dA0 = swz64(r0, c0), dA1 = swz64(r0, c0 + 4);
    const uint32_t dA2 = swz64(r0 + 64, c0), dA3 = swz64(r0 + 64, c0 + 4);

    const char* pAh = (const char*)Ah_g + (size_t)(bm + r0) * 1024 + c0 * 16;
    const char* pAl = (MODE == 0) ? (const char*)Al_g + (size_t)(bm + r0) * 1024 + c0 * 16
                                  : nullptr;
    const char* pBh = (const char*)Bh_g + (size_t)(bn + r0) * 1024 + c0 * 16;
    const char* pBl = (MODE == 0) ? (const char*)Bl_g + (size_t)(bn + r0) * 1024 + c0 * 16
                                  : nullptr;

    float acc[4][4][4];
#pragma unroll
    for (int mi = 0; mi < 4; mi++)
#pragma unroll
        for (int ni = 0; ni < 4; ni++)
#pragma unroll
            for (int j = 0; j < 4; j++) acc[mi][ni][j] = 0.f;

    const int arow = lane & 15, asel = lane >> 4;
    const int brow = ((lane >> 4) << 3) + (lane & 7);
    const int bsel = (lane >> 3) & 1;

    auto issue_stage = [&](uint32_t sb, int koff) {
        if (MODE == 0) {
            CPA(sb + d32,                pAh + koff);
            CPA(sb + d32 + 4096,         pAh + koff + 65536);
            CPA(sb + 8192 + d32,         pAl + koff);
            CPA(sb + 8192 + d32 + 4096,  pAl + koff + 65536);
            CPA(sb + 16384 + d32,        pBh + koff);
            CPA(sb + 16384 + d32 + 4096, pBh + koff + 65536);
            CPA(sb + 24576 + d32,        pBl + koff);
            CPA(sb + 24576 + d32 + 4096, pBl + koff + 65536);
        } else {
            CPA(sb + dA0,         pAh + koff);
            CPA(sb + dA1,         pAh + koff + 64);
            CPA(sb + dA2,         pAh + koff + 65536);
            CPA(sb + dA3,         pAh + koff + 65536 + 64);
            CPA(sb + 16384 + dA0, pBh + koff);
            CPA(sb + 16384 + dA1, pBh + koff + 64);
            CPA(sb + 16384 + dA2, pBh + koff + 65536);
            CPA(sb + 16384 + dA3, pBh + koff + 65536 + 64);
        }
        CPA_COMMIT();
    };

    constexpr int KBYTES = (MODE == 0) ? 64 : 128;
#pragma unroll
    for (int g = 0; g < DEPTH - 1; g++) issue_stage(sbase + g * STAGE_B, g * KBYTES);

    // Precompute fill values (dist only)
    float s0 = 0.f, invt = 0.f;
    float* sval = (float*)(sm_ + DEPTH * STAGE_B);
    if (MODE == 1) {
        s0 = scales[0];
        invt = 1.0f / fmaxf(temp[0], TEMP_MIN);
        int cbase = NK + blockIdx.x * 384;
        for (int i = tid; i < 384; i += 256) sval[i] = -cn[cbase + i] * invt;
    }
    const int fbase = (MODE == 1) ? NK + blockIdx.x * 384 : 0;

#pragma unroll 1
    for (int kc = 0; kc < NCH; kc++) {
        if (kc + DEPTH - 1 < NCH) {
            CPA_WAIT(DEPTH - 2);
            __syncthreads();
            issue_stage(sbase + ((kc + DEPTH - 1) % DEPTH) * STAGE_B, (kc + DEPTH - 1) * KBYTES);
        } else {
            int rem = NCH - 1 - kc;
            cpa_wait_dyn(rem < DEPTH - 2 ? rem : DEPTH - 2);
            __syncthreads();
        }
        const uint32_t ah = sbase + (kc % DEPTH) * STAGE_B;
        const uint32_t al = ah + 8192;
        const uint32_t bh = ah + OFF_B;
        const uint32_t bl = ah + 24576;

        // Interleaved fill stores (dist: 6 float4/thread/chunk, streaming)
        if (MODE == 1) {
#pragma unroll
            for (int jj = 0; jj < 6; jj++) {
                int idx = tid + (kc * 6 + jj) * 256;  // < 12288
                int row = idx / 96;
                int cc = (idx - row * 96) * 4;
                float4 v = *(float4*)&sval[cc];
                __stcs((float4*)&C[(size_t)(bm + row) * ldc + fbase + cc], v);
            }
        }

#pragma unroll
        for (int ks = 0; ks < KSTEPS; ks++) {
            const int ccA = ks * 2 + asel;
            const int ccB = ks * 2 + bsel;
            uint32_t bfh[4][2], bfl[4][2];
            {
                int rb = wn + brow;
                uint32_t o1, o2;
                if (MODE == 0) { o1 = swz32(rb, ccB); o2 = swz32(rb + 16, ccB); }
                else           { o1 = swz64(rb, ccB); o2 = swz64(rb + 16, ccB); }
                uint32_t t4[4];
                ldm_x4(t4, bh + o1);
                bfh[0][0] = t4[0]; bfh[0][1] = t4[1]; bfh[1][0] = t4[2]; bfh[1][1] = t4[3];
                ldm_x4(t4, bh + o2);
                bfh[2][0] = t4[0]; bfh[2][1] = t4[1]; bfh[3][0] = t4[2]; bfh[3][1] = t4[3];
                if (MODE == 0) {
                    ldm_x4(t4, bl + o1);
                    bfl[0][0] = t4[0]; bfl[0][1] = t4[1]; bfl[1][0] = t4[2]; bfl[1][1] = t4[3];
                    ldm_x4(t4, bl + o2);
                    bfl[2][0] = t4[0]; bfl[2][1] = t4[1]; bfl[3][0] = t4[2]; bfl[3][1] = t4[3];
                }
            }
#pragma unroll
            for (int mi = 0; mi < 4; mi++) {
                int ra = wm + mi * 16 + arow;
                uint32_t ao = (MODE == 0) ? swz32(ra, ccA) : swz64(ra, ccA);
                uint32_t afh[4];
                ldm_x4(afh, ah + ao);
#pragma unroll
                for (int ni = 0; ni < 4; ni++) mma16816(acc[mi][ni], afh, bfh[ni]);
                if (MODE == 0) {
#pragma unroll
                    for (int ni = 0; ni < 4; ni++) mma16816(acc[mi][ni], afh, bfl[ni]);
                    uint32_t afl[4];
                    ldm_x4(afl, al + ao);
#pragma unroll
                    for (int ni = 0; ni < 4; ni++) mma16816(acc[mi][ni], afl, bfh[ni]);
                }
            }
        }
    }

    // Epilogue (logits / bias; fill already done in-loop)
    const int gid = lane >> 2, t4i = lane & 3;
#pragma unroll
    for (int mi = 0; mi < 4; mi++) {
        int r = bm + wm + mi * 16 + gid;
#pragma unroll
        for (int ni = 0; ni < 4; ni++) {
            int c = bn + wn + ni * 8 + t4i * 2;
            float* a4 = acc[mi][ni];
            if (MODE == 0) {
                float b0 = bias[c], b1 = bias[c + 1];
                *(float2*)&C[(size_t)r * ldc + c] = make_float2(a4[0] + b0, a4[1] + b1);
                *(float2*)&C[(size_t)(r + 8) * ldc + c] = make_float2(a4[2] + b0, a4[3] + b1);
            } else {
                float m2s = 2.0f * s0;
                float cv0 = cn[c], cv1 = cn[c + 1];
                float rv0 = rn[r], rv1 = rn[r + 8];
                float2 o0, o1;
                o0.x = -(rv0 + cv0 - m2s * a4[0]) * invt;
                o0.y = -(rv0 + cv1 - m2s * a4[1]) * invt;
                o1.x = -(rv1 + cv0 - m2s * a4[2]) * invt;
                o1.y = -(rv1 + cv1 - m2s * a4[3]) * invt;
                __stcs((float2*)&C[(size_t)r * ldc + c], o0);
                __stcs((float2*)&C[(size_t)(r + 8) * ldc + c], o1);
            }
        }
    }
}

// ---------------------------------------------------------------------------
// Merged fp32 -> bf16 hi/lo converter: features (NB*ND) then W_proj (ND*ND).
// One launch covers both tensors (float4 granularity).
// ---------------------------------------------------------------------------
static constexpr int FEAT4 = NB * ND / 4;  // 1,048,576
static constexpr int W4 = ND * ND / 4;     //    65,536

__global__ void __launch_bounds__(256) conv_all_kernel(const float* __restrict__ feat,
                                                       const float* __restrict__ wp) {
    int idx = blockIdx.x * 256 + threadIdx.x;
    if (idx < FEAT4) {
        float4 v = ((const float4*)feat)[idx];
        uint2 hh, ll;
        cvt4(v, hh, ll);
        ((uint2*)g_fh)[idx] = hh;
        ((uint2*)g_fl)[idx] = ll;
    } else {
        int j = idx - FEAT4;  // < W4 by grid sizing
        float4 v = ((const float4*)wp)[j];
        uint2 hh, ll;
        cvt4(v, hh, ll);
        ((uint2*)g_wh)[j] = hh;
        ((uint2*)g_wl)[j] = ll;
    }
}

// ---------------------------------------------------------------------------
__global__ void __launch_bounds__(256) cbnorm_kernel(const float* __restrict__ cb,
                                                     float* __restrict__ cn) {
    int row = blockIdx.x * 8 + (threadIdx.x >> 5);
    int lane = threadIdx.x & 31;
    const float* p = cb + (size_t)row * ND;
    float s = 0.f;
#pragma unroll
    for (int i = 0; i < 4; i++) {
        int off = (lane + i * 32) * 4;
        float4 v = *(const float4*)&p[off];
        s += v.x * v.x + v.y * v.y + v.z * v.z + v.w * v.w;
        if (row < NK) {
            __nv_bfloat162 h0 = __floats2bfloat162_rn(v.x, v.y);
            __nv_bfloat162 h1 = __floats2bfloat162_rn(v.z, v.w);
            uint2 hh;
            hh.x = *(uint32_t*)&h0; hh.y = *(uint32_t*)&h1;
            *(uint2*)&g_ch[(size_t)row * ND + off] = hh;
        }
    }
#pragma unroll
    for (int o = 16; o > 0; o >>= 1) s += __shfl_xor_sync(0xffffffffu, s, o);
    if (lane == 0) cn[row] = s;
}

// ---------------------------------------------------------------------------
// Warp-per-row fused LN(affine)+ReLU -> x hi bf16, LN2 (no affine), row norm.
// ---------------------------------------------------------------------------
__global__ void __launch_bounds__(256) ln_kernel(const float* __restrict__ lng,
                                                 const float* __restrict__ lnb,
                                                 const float* __restrict__ scales,
                                                 float* __restrict__ q_out) {
    int b = blockIdx.x * 8 + (threadIdx.x >> 5);
    int lane = threadIdx.x & 31;
    const float* y = g_y + (size_t)b * ND;

    float4 v[4];
    float s = 0.f, s2 = 0.f;
#pragma unroll
    for (int i = 0; i < 4; i++) {
        v[i] = *(const float4*)&y[(lane + i * 32) * 4];
        s += v[i].x + v[i].y + v[i].z + v[i].w;
        s2 += v[i].x * v[i].x + v[i].y * v[i].y + v[i].z * v[i].z + v[i].w * v[i].w;
    }
#pragma unroll
    for (int o = 16; o > 0; o >>= 1) {
        s += __shfl_xor_sync(0xffffffffu, s, o);
        s2 += __shfl_xor_sync(0xffffffffu, s2, o);
    }
    float mu = s * (1.0f / ND);
    float var = s2 * (1.0f / ND) - mu * mu;
    float rstd = rsqrtf(var + EPSN);

    float x[16];
    float ss = 0.f, ss2 = 0.f;
    float s0 = scales[0];
#pragma unroll
    for (int i = 0; i < 4; i++) {
        int off = (lane + i * 32) * 4;
        float4 g = *(const float4*)&lng[off];
        float4 bb = *(const float4*)&lnb[off];
        float* vi = &v[i].x;
        float* gi = &g.x;
        float* bi = &bb.x;
#pragma unroll
        for (int j = 0; j < 4; j++) {
            float xv = fmaxf((vi[j] - mu) * rstd * gi[j] + bi[j], 0.0f);
            x[i * 4 + j] = xv;
            float sv = s0 * xv;
            ss += sv;
            ss2 += sv * sv;
        }
        __nv_bfloat162 h0 = __floats2bfloat162_rn(x[i * 4], x[i * 4 + 1]);
        __nv_bfloat162 h1 = __floats2bfloat162_rn(x[i * 4 + 2], x[i * 4 + 3]);
        uint2 hh;
        hh.x = *(uint32_t*)&h0; hh.y = *(uint32_t*)&h1;
        *(uint2*)&g_xh[(size_t)b * ND + off] = hh;
    }
#pragma unroll
    for (int o = 16; o > 0; o >>= 1) {
        ss += __shfl_xor_sync(0xffffffffu, ss, o);
        ss2 += __shfl_xor_sync(0xffffffffu, ss2, o);
    }
    if (lane == 0) g_rn[b] = ss2;
    float mu2 = ss * (1.0f / ND);
    float var2 = ss2 * (1.0f / ND) - mu2 * mu2;
    float rstd2 = rsqrtf(var2 + EPSN);
#pragma unroll
    for (int i = 0; i < 4; i++) {
        int off = (lane + i * 32) * 4;
        float4 qo;
        qo.x = (s0 * x[i * 4 + 0] - mu2) * rstd2;
        qo.y = (s0 * x[i * 4 + 1] - mu2) * rstd2;
        qo.z = (s0 * x[i * 4 + 2] - mu2) * rstd2;
        qo.w = (s0 * x[i * 4 + 3] - mu2) * rstd2;
        *(float4*)&q_out[(size_t)b * ND + off] = qo;
    }
}

// ---------------------------------------------------------------------------
extern "C" void kernel_launch(void* const* d_in, const int* in_sizes, int n_in,
                              void* d_out, int out_size) {
    const float* features = (const float*)d_in[0];
    const float* Wp       = (const float*)d_in[1];
    const float* bproj    = (const float*)d_in[2];
    const float* lng      = (const float*)d_in[3];
    const float* lnb      = (const float*)d_in[4];
    const float* cbs      = (const float*)d_in[5];
    const float* scales   = (const float*)d_in[6];
    const float* temp     = (const float*)d_in[7];
    float* out = (float*)d_out;
    float* out_q = out + (size_t)NB * NL * NK;

    float *dy, *drn, *dcn;
    __nv_bfloat16 *dfh, *dfl, *dwh, *dwl, *dxh, *dch;
    cudaGetSymbolAddress((void**)&dy, g_y);
    cudaGetSymbolAddress((void**)&drn, g_rn);
    cudaGetSymbolAddress((void**)&dcn, g_cn);
    cudaGetSymbolAddress((void**)&dfh, g_fh);
    cudaGetSymbolAddress((void**)&dfl, g_fl);
    cudaGetSymbolAddress((void**)&dwh, g_wh);
    cudaGetSymbolAddress((void**)&dwl, g_wl);
    cudaGetSymbolAddress((void**)&dxh, g_xh);
    cudaGetSymbolAddress((void**)&dch, g_ch);

    const int SMEM_PROJ = 3 * 32768;
    const int SMEM_DIST = 3 * 32768 + 1536;
    cudaFuncSetAttribute((gemm_mma<0, 3>), cudaFuncAttributeMaxDynamicSharedMemorySize, SMEM_PROJ);
    cudaFuncSetAttribute((gemm_mma<1, 3>), cudaFuncAttributeMaxDynamicSharedMemorySize, SMEM_DIST);

    // 0. preconvert features + W_proj to bf16 hi/lo (single merged launch)
    conv_all_kernel<<<(FEAT4 + W4) / 256, 256>>>(features, Wp);
    // 1. proj GEMM (3-pass split bf16, BK=32)
    {
        dim3 grid(ND / BN, NB / BM);
        gemm_mma<0, 3><<<grid, 256, SMEM_PROJ>>>(dfh, dfl, dwh, dwl, dy, ND, bproj,
                                                 nullptr, nullptr, nullptr, nullptr);
    }
    // 2. fused LN + ReLU + LN2 + rownorm (1 row per warp)
    ln_kernel<<<NB / 8, 256>>>(lng, lnb, scales, out_q);
    // 3. codebook norms + codebook0 hi
    cbnorm_kernel<<<(NL * NK) / 8, 256>>>(cbs, dcn);
    // 4. dist GEMM (1-pass bf16, BK=64, DEPTH=3) + logits + interleaved fill
    {
        dim3 grid(NK / BN, NB / BM);
        gemm_mma<1, 3><<<grid, 256, SMEM_DIST>>>(dxh, nullptr, dch, nullptr, out, NL * NK,
                                                 nullptr, drn, dcn, scales, temp);
    }
}

// round 16
// speedup vs baseline: 1.0536x; 1.0282x over previous
#include <cuda_runtime.h>
#include <cuda_bf16.h>
#include <cstdint>

#define NB 8192
#define ND 512
#define NK 2048
#define NL 4
#define EPSN 1e-5f
#define TEMP_MIN 0.01f

#define BM 128
#define BN 128

// Scratch (static device arrays; no allocations)
static __device__ float g_y[NB * ND];
static __device__ __align__(16) __nv_bfloat16 g_fh[NB * ND];
static __device__ __align__(16) __nv_bfloat16 g_fl[NB * ND];
static __device__ __align__(16) __nv_bfloat16 g_wh[ND * ND];
static __device__ __align__(16) __nv_bfloat16 g_wl[ND * ND];
static __device__ __align__(16) __nv_bfloat16 g_xh[NB * ND];
static __device__ __align__(16) __nv_bfloat16 g_ch[NK * ND];
static __device__ float g_rn[NB];
static __device__ float g_cn[NL * NK];

// ---------------------------------------------------------------------------
__device__ __forceinline__ uint32_t smem_u32(const void* p) {
    uint32_t a;
    asm("{ .reg .u64 t; cvta.to.shared.u64 t, %1; cvt.u32.u64 %0, t; }" : "=r"(a) : "l"(p));
    return a;
}

#define CPA(dst, src) \
    asm volatile("cp.async.cg.shared.global [%0], [%1], 16;" :: "r"(dst), "l"(src) : "memory")
#define CPA_COMMIT() asm volatile("cp.async.commit_group;" ::: "memory")
#define CPA_WAIT(N)  asm volatile("cp.async.wait_group %0;" :: "n"(N) : "memory")

__device__ __forceinline__ void cpa_wait_dyn(int n) {
    switch (n) {
        case 0: CPA_WAIT(0); break;
        case 1: CPA_WAIT(1); break;
        case 2: CPA_WAIT(2); break;
        case 3: CPA_WAIT(3); break;
        default: CPA_WAIT(4); break;
    }
}

__device__ __forceinline__ void ldm_x4(uint32_t* r, uint32_t addr) {
    asm volatile("ldmatrix.sync.aligned.m8n8.x4.shared.b16 {%0,%1,%2,%3}, [%4];"
                 : "=r"(r[0]), "=r"(r[1]), "=r"(r[2]), "=r"(r[3]) : "r"(addr));
}

__device__ __forceinline__ void mma16816(float* c, const uint32_t* a, const uint32_t* b) {
    asm volatile(
        "mma.sync.aligned.m16n8k16.row.col.f32.bf16.bf16.f32 "
        "{%0,%1,%2,%3}, {%4,%5,%6,%7}, {%8,%9}, {%0,%1,%2,%3};"
        : "+f"(c[0]), "+f"(c[1]), "+f"(c[2]), "+f"(c[3])
        : "r"(a[0]), "r"(a[1]), "r"(a[2]), "r"(a[3]), "r"(b[0]), "r"(b[1]));
}

__device__ __forceinline__ void cvt4(float4 v, uint2& h, uint2& l) {
    __nv_bfloat162 h0 = __floats2bfloat162_rn(v.x, v.y);
    __nv_bfloat162 h1 = __floats2bfloat162_rn(v.z, v.w);
    float lx = v.x - __bfloat162float(h0.x);
    float ly = v.y - __bfloat162float(h0.y);
    float lz = v.z - __bfloat162float(h1.x);
    float lw = v.w - __bfloat162float(h1.y);
    __nv_bfloat162 l0 = __floats2bfloat162_rn(lx, ly);
    __nv_bfloat162 l1 = __floats2bfloat162_rn(lz, lw);
    h.x = *(uint32_t*)&h0; h.y = *(uint32_t*)&h1;
    l.x = *(uint32_t*)&l0; l.y = *(uint32_t*)&l1;
}

// BK=32 layout: 64B rows, 4 x 16B chunks, 2-row-group XOR swizzle
__device__ __forceinline__ uint32_t swz32(int row, int cc) {
    return (uint32_t)(row * 64 + ((cc ^ ((row >> 1) & 3)) << 4));
}
// BK=64 layout: 128B rows, 8 x 16B chunks, full SW128 row swizzle
__device__ __forceinline__ uint32_t swz64(int row, int cc) {
    return (uint32_t)(row * 128 + ((cc ^ (row & 7)) << 4));
}

// ---------------------------------------------------------------------------
// Split/plain-bf16 tensor GEMM, cp.async pipeline, 2 CTAs/SM.
// MODE 0 (proj): 3-pass split-bf16, BK=32, DEPTH=3, +bias.
// MODE 1 (dist): 1-pass plain bf16, BK=64, DEPTH=3,
//                logits epilogue + interleaved levels-1..3 fill.
// ---------------------------------------------------------------------------
template <int MODE, int DEPTH>
__global__ void __launch_bounds__(256, 2) gemm_mma(
    const __nv_bfloat16* __restrict__ Ah_g, const __nv_bfloat16* __restrict__ Al_g,
    const __nv_bfloat16* __restrict__ Bh_g, const __nv_bfloat16* __restrict__ Bl_g,
    float* __restrict__ C, int ldc,
    const float* __restrict__ bias, const float* __restrict__ rn,
    const float* __restrict__ cn, const float* __restrict__ scales,
    const float* __restrict__ temp) {
    constexpr int STAGE_B = 32768;                    // both modes: 32 KB/stage
    constexpr int NCH = (MODE == 0) ? 16 : 8;         // k-chunks
    constexpr int KSTEPS = (MODE == 0) ? 2 : 4;       // k16 steps per chunk
    constexpr uint32_t OFF_B = 16384;
    extern __shared__ char sm_[];
    const int tid = threadIdx.x;
    const int wid = tid >> 5, lane = tid & 31;
    const int bm = blockIdx.y * BM, bn = blockIdx.x * BN;
    const int wm = (wid & 1) * 64;
    const int wn = (wid >> 1) * 32;
    const uint32_t sbase = smem_u32(sm_);

    // staging coords
    const int r0 = tid >> 2, c0 = tid & 3;
    const uint32_t d32 = swz32(r0, c0);
    const uint32_t dA0 = swz64(r0, c0), dA1 = swz64(r0, c0 + 4);
    const uint32_t dA2 = swz64(r0 + 64, c0), dA3 = swz64(r0 + 64, c0 + 4);

    const char* pAh = (const char*)Ah_g + (size_t)(bm + r0) * 1024 + c0 * 16;
    const char* pAl = (MODE == 0) ? (const char*)Al_g + (size_t)(bm + r0) * 1024 + c0 * 16
                                  : nullptr;
    const char* pBh = (const char*)Bh_g + (size_t)(bn + r0) * 1024 + c0 * 16;
    const char* pBl = (MODE == 0) ? (const char*)Bl_g + (size_t)(bn + r0) * 1024 + c0 * 16
                                  : nullptr;

    float acc[4][4][4];
#pragma unroll
    for (int mi = 0; mi < 4; mi++)
#pragma unroll
        for (int ni = 0; ni < 4; ni++)
#pragma unroll
            for (int j = 0; j < 4; j++) acc[mi][ni][j] = 0.f;

    const int arow = lane & 15, asel = lane >> 4;
    const int brow = ((lane >> 4) << 3) + (lane & 7);
    const int bsel = (lane >> 3) & 1;

    auto issue_stage = [&](uint32_t sb, int koff) {
        if (MODE == 0) {
            CPA(sb + d32,                pAh + koff);
            CPA(sb + d32 + 4096,         pAh + koff + 65536);
            CPA(sb + 8192 + d32,         pAl + koff);
            CPA(sb + 8192 + d32 + 4096,  pAl + koff + 65536);
            CPA(sb + 16384 + d32,        pBh + koff);
            CPA(sb + 16384 + d32 + 4096, pBh + koff + 65536);
            CPA(sb + 24576 + d32,        pBl + koff);
            CPA(sb + 24576 + d32 + 4096, pBl + koff + 65536);
        } else {
            CPA(sb + dA0,         pAh + koff);
            CPA(sb + dA1,         pAh + koff + 64);
            CPA(sb + dA2,         pAh + koff + 65536);
            CPA(sb + dA3,         pAh + koff + 65536 + 64);
            CPA(sb + 16384 + dA0, pBh + koff);
            CPA(sb + 16384 + dA1, pBh + koff + 64);
            CPA(sb + 16384 + dA2, pBh + koff + 65536);
            CPA(sb + 16384 + dA3, pBh + koff + 65536 + 64);
        }
        CPA_COMMIT();
    };

    constexpr int KBYTES = (MODE == 0) ? 64 : 128;
#pragma unroll
    for (int g = 0; g < DEPTH - 1; g++) issue_stage(sbase + g * STAGE_B, g * KBYTES);

    // Precompute fill values (dist only)
    float s0 = 0.f, invt = 0.f;
    float* sval = (float*)(sm_ + DEPTH * STAGE_B);
    if (MODE == 1) {
        s0 = scales[0];
        invt = 1.0f / fmaxf(temp[0], TEMP_MIN);
        int cbase = NK + blockIdx.x * 384;
        for (int i = tid; i < 384; i += 256) sval[i] = -cn[cbase + i] * invt;
    }
    const int fbase = (MODE == 1) ? NK + blockIdx.x * 384 : 0;

#pragma unroll 1
    for (int kc = 0; kc < NCH; kc++) {
        if (kc + DEPTH - 1 < NCH) {
            CPA_WAIT(DEPTH - 2);
            __syncthreads();
            issue_stage(sbase + ((kc + DEPTH - 1) % DEPTH) * STAGE_B, (kc + DEPTH - 1) * KBYTES);
        } else {
            int rem = NCH - 1 - kc;
            cpa_wait_dyn(rem < DEPTH - 2 ? rem : DEPTH - 2);
            __syncthreads();
        }
        const uint32_t ah = sbase + (kc % DEPTH) * STAGE_B;
        const uint32_t al = ah + 8192;
        const uint32_t bh = ah + OFF_B;
        const uint32_t bl = ah + 24576;

        // Interleaved fill stores (dist: 6 float4/thread/chunk, streaming)
        if (MODE == 1) {
#pragma unroll
            for (int jj = 0; jj < 6; jj++) {
                int idx = tid + (kc * 6 + jj) * 256;  // < 12288
                int row = idx / 96;
                int cc = (idx - row * 96) * 4;
                float4 v = *(float4*)&sval[cc];
                __stcs((float4*)&C[(size_t)(bm + row) * ldc + fbase + cc], v);
            }
        }

#pragma unroll
        for (int ks = 0; ks < KSTEPS; ks++) {
            const int ccA = ks * 2 + asel;
            const int ccB = ks * 2 + bsel;
            uint32_t bfh[4][2], bfl[4][2];
            {
                int rb = wn + brow;
                uint32_t o1, o2;
                if (MODE == 0) { o1 = swz32(rb, ccB); o2 = swz32(rb + 16, ccB); }
                else           { o1 = swz64(rb, ccB); o2 = swz64(rb + 16, ccB); }
                uint32_t t4[4];
                ldm_x4(t4, bh + o1);
                bfh[0][0] = t4[0]; bfh[0][1] = t4[1]; bfh[1][0] = t4[2]; bfh[1][1] = t4[3];
                ldm_x4(t4, bh + o2);
                bfh[2][0] = t4[0]; bfh[2][1] = t4[1]; bfh[3][0] = t4[2]; bfh[3][1] = t4[3];
                if (MODE == 0) {
                    ldm_x4(t4, bl + o1);
                    bfl[0][0] = t4[0]; bfl[0][1] = t4[1]; bfl[1][0] = t4[2]; bfl[1][1] = t4[3];
                    ldm_x4(t4, bl + o2);
                    bfl[2][0] = t4[0]; bfl[2][1] = t4[1]; bfl[3][0] = t4[2]; bfl[3][1] = t4[3];
                }
            }
#pragma unroll
            for (int mi = 0; mi < 4; mi++) {
                int ra = wm + mi * 16 + arow;
                uint32_t ao = (MODE == 0) ? swz32(ra, ccA) : swz64(ra, ccA);
                uint32_t afh[4];
                ldm_x4(afh, ah + ao);
#pragma unroll
                for (int ni = 0; ni < 4; ni++) mma16816(acc[mi][ni], afh, bfh[ni]);
                if (MODE == 0) {
#pragma unroll
                    for (int ni = 0; ni < 4; ni++) mma16816(acc[mi][ni], afh, bfl[ni]);
                    uint32_t afl[4];
                    ldm_x4(afl, al + ao);
#pragma unroll
                    for (int ni = 0; ni < 4; ni++) mma16816(acc[mi][ni], afl, bfh[ni]);
                }
            }
        }
    }

    // Epilogue (logits / bias; fill already done in-loop)
    const int gid = lane >> 2, t4i = lane & 3;
#pragma unroll
    for (int mi = 0; mi < 4; mi++) {
        int r = bm + wm + mi * 16 + gid;
#pragma unroll
        for (int ni = 0; ni < 4; ni++) {
            int c = bn + wn + ni * 8 + t4i * 2;
            float* a4 = acc[mi][ni];
            if (MODE == 0) {
                float b0 = bias[c], b1 = bias[c + 1];
                *(float2*)&C[(size_t)r * ldc + c] = make_float2(a4[0] + b0, a4[1] + b1);
                *(float2*)&C[(size_t)(r + 8) * ldc + c] = make_float2(a4[2] + b0, a4[3] + b1);
            } else {
                float m2s = 2.0f * s0;
                float cv0 = cn[c], cv1 = cn[c + 1];
                float rv0 = rn[r], rv1 = rn[r + 8];
                float2 o0, o1;
                o0.x = -(rv0 + cv0 - m2s * a4[0]) * invt;
                o0.y = -(rv0 + cv1 - m2s * a4[1]) * invt;
                o1.x = -(rv1 + cv0 - m2s * a4[2]) * invt;
                o1.y = -(rv1 + cv1 - m2s * a4[3]) * invt;
                __stcs((float2*)&C[(size_t)r * ldc + c], o0);
                __stcs((float2*)&C[(size_t)(r + 8) * ldc + c], o1);
            }
        }
    }
}

// ---------------------------------------------------------------------------
// Merged preprocessing kernel (single launch):
//   blocks [0, CONV_BLKS): fp32 -> bf16 hi/lo for features then W_proj
//   blocks [CONV_BLKS, CONV_BLKS+CB_BLKS): codebook row norms + codebook0 hi
// ---------------------------------------------------------------------------
static constexpr int FEAT4 = NB * ND / 4;       // 1,048,576 float4
static constexpr int W4 = ND * ND / 4;          //    65,536 float4
static constexpr int CONV_BLKS = (FEAT4 + W4) / 256;  // 4352
static constexpr int CB_BLKS = (NL * NK) / 8;         // 1024

__global__ void __launch_bounds__(256) prep_kernel(const float* __restrict__ feat,
                                                   const float* __restrict__ wp,
                                                   const float* __restrict__ cb,
                                                   float* __restrict__ cn) {
    if (blockIdx.x < CONV_BLKS) {
        int idx = blockIdx.x * 256 + threadIdx.x;
        if (idx < FEAT4) {
            float4 v = ((const float4*)feat)[idx];
            uint2 hh, ll;
            cvt4(v, hh, ll);
            ((uint2*)g_fh)[idx] = hh;
            ((uint2*)g_fl)[idx] = ll;
        } else {
            int j = idx - FEAT4;  // < W4 by grid sizing
            float4 v = ((const float4*)wp)[j];
            uint2 hh, ll;
            cvt4(v, hh, ll);
            ((uint2*)g_wh)[j] = hh;
            ((uint2*)g_wl)[j] = ll;
        }
    } else {
        int row = (blockIdx.x - CONV_BLKS) * 8 + (threadIdx.x >> 5);
        int lane = threadIdx.x & 31;
        const float* p = cb + (size_t)row * ND;
        float s = 0.f;
#pragma unroll
        for (int i = 0; i < 4; i++) {
            int off = (lane + i * 32) * 4;
            float4 v = *(const float4*)&p[off];
            s += v.x * v.x + v.y * v.y + v.z * v.z + v.w * v.w;
            if (row < NK) {
                __nv_bfloat162 h0 = __floats2bfloat162_rn(v.x, v.y);
                __nv_bfloat162 h1 = __floats2bfloat162_rn(v.z, v.w);
                uint2 hh;
                hh.x = *(uint32_t*)&h0; hh.y = *(uint32_t*)&h1;
                *(uint2*)&g_ch[(size_t)row * ND + off] = hh;
            }
        }
#pragma unroll
        for (int o = 16; o > 0; o >>= 1) s += __shfl_xor_sync(0xffffffffu, s, o);
        if (lane == 0) cn[row] = s;
    }
}

// ---------------------------------------------------------------------------
// Warp-per-row fused LN(affine)+ReLU -> x hi bf16, LN2 (no affine), row norm.
// ---------------------------------------------------------------------------
__global__ void __launch_bounds__(256) ln_kernel(const float* __restrict__ lng,
                                                 const float* __restrict__ lnb,
                                                 const float* __restrict__ scales,
                                                 float* __restrict__ q_out) {
    int b = blockIdx.x * 8 + (threadIdx.x >> 5);
    int lane = threadIdx.x & 31;
    const float* y = g_y + (size_t)b * ND;

    float4 v[4];
    float s = 0.f, s2 = 0.f;
#pragma unroll
    for (int i = 0; i < 4; i++) {
        v[i] = *(const float4*)&y[(lane + i * 32) * 4];
        s += v[i].x + v[i].y + v[i].z + v[i].w;
        s2 += v[i].x * v[i].x + v[i].y * v[i].y + v[i].z * v[i].z + v[i].w * v[i].w;
    }
#pragma unroll
    for (int o = 16; o > 0; o >>= 1) {
        s += __shfl_xor_sync(0xffffffffu, s, o);
        s2 += __shfl_xor_sync(0xffffffffu, s2, o);
    }
    float mu = s * (1.0f / ND);
    float var = s2 * (1.0f / ND) - mu * mu;
    float rstd = rsqrtf(var + EPSN);

    float x[16];
    float ss = 0.f, ss2 = 0.f;
    float s0 = scales[0];
#pragma unroll
    for (int i = 0; i < 4; i++) {
        int off = (lane + i * 32) * 4;
        float4 g = *(const float4*)&lng[off];
        float4 bb = *(const float4*)&lnb[off];
        float* vi = &v[i].x;
        float* gi = &g.x;
        float* bi = &bb.x;
#pragma unroll
        for (int j = 0; j < 4; j++) {
            float xv = fmaxf((vi[j] - mu) * rstd * gi[j] + bi[j], 0.0f);
            x[i * 4 + j] = xv;
            float sv = s0 * xv;
            ss += sv;
            ss2 += sv * sv;
        }
        __nv_bfloat162 h0 = __floats2bfloat162_rn(x[i * 4], x[i * 4 + 1]);
        __nv_bfloat162 h1 = __floats2bfloat162_rn(x[i * 4 + 2], x[i * 4 + 3]);
        uint2 hh;
        hh.x = *(uint32_t*)&h0; hh.y = *(uint32_t*)&h1;
        *(uint2*)&g_xh[(size_t)b * ND + off] = hh;
    }
#pragma unroll
    for (int o = 16; o > 0; o >>= 1) {
        ss += __shfl_xor_sync(0xffffffffu, ss, o);
        ss2 += __shfl_xor_sync(0xffffffffu, ss2, o);
    }
    if (lane == 0) g_rn[b] = ss2;
    float mu2 = ss * (1.0f / ND);
    float var2 = ss2 * (1.0f / ND) - mu2 * mu2;
    float rstd2 = rsqrtf(var2 + EPSN);
#pragma unroll
    for (int i = 0; i < 4; i++) {
        int off = (lane + i * 32) * 4;
        float4 qo;
        qo.x = (s0 * x[i * 4 + 0] - mu2) * rstd2;
        qo.y = (s0 * x[i * 4 + 1] - mu2) * rstd2;
        qo.z = (s0 * x[i * 4 + 2] - mu2) * rstd2;
        qo.w = (s0 * x[i * 4 + 3] - mu2) * rstd2;
        *(float4*)&q_out[(size_t)b * ND + off] = qo;
    }
}

// ---------------------------------------------------------------------------
extern "C" void kernel_launch(void* const* d_in, const int* in_sizes, int n_in,
                              void* d_out, int out_size) {
    const float* features = (const float*)d_in[0];
    const float* Wp       = (const float*)d_in[1];
    const float* bproj    = (const float*)d_in[2];
    const float* lng      = (const float*)d_in[3];
    const float* lnb      = (const float*)d_in[4];
    const float* cbs      = (const float*)d_in[5];
    const float* scales   = (const float*)d_in[6];
    const float* temp     = (const float*)d_in[7];
    float* out = (float*)d_out;
    float* out_q = out + (size_t)NB * NL * NK;

    float *dy, *drn, *dcn;
    __nv_bfloat16 *dfh, *dfl, *dwh, *dwl, *dxh, *dch;
    cudaGetSymbolAddress((void**)&dy, g_y);
    cudaGetSymbolAddress((void**)&drn, g_rn);
    cudaGetSymbolAddress((void**)&dcn, g_cn);
    cudaGetSymbolAddress((void**)&dfh, g_fh);
    cudaGetSymbolAddress((void**)&dfl, g_fl);
    cudaGetSymbolAddress((void**)&dwh, g_wh);
    cudaGetSymbolAddress((void**)&dwl, g_wl);
    cudaGetSymbolAddress((void**)&dxh, g_xh);
    cudaGetSymbolAddress((void**)&dch, g_ch);

    const int SMEM_PROJ = 3 * 32768;
    const int SMEM_DIST = 3 * 32768 + 1536;
    cudaFuncSetAttribute((gemm_mma<0, 3>), cudaFuncAttributeMaxDynamicSharedMemorySize, SMEM_PROJ);
    cudaFuncSetAttribute((gemm_mma<1, 3>), cudaFuncAttributeMaxDynamicSharedMemorySize, SMEM_DIST);

    // 0. merged preprocessing: conv(features+W_proj) + cbnorm + codebook0-hi
    prep_kernel<<<CONV_BLKS + CB_BLKS, 256>>>(features, Wp, cbs, dcn);
    // 1. proj GEMM (3-pass split bf16, BK=32)
    {
        dim3 grid(ND / BN, NB / BM);
        gemm_mma<0, 3><<<grid, 256, SMEM_PROJ>>>(dfh, dfl, dwh, dwl, dy, ND, bproj,
                                                 nullptr, nullptr, nullptr, nullptr);
    }
    // 2. fused LN + ReLU + LN2 + rownorm (1 row per warp)
    ln_kernel<<<NB / 8, 256>>>(lng, lnb, scales, out_q);
    // 3. dist GEMM (1-pass bf16, BK=64, DEPTH=3) + logits + interleaved fill
    {
        dim3 grid(NK / BN, NB / BM);
        gemm_mma<1, 3><<<grid, 256, SMEM_DIST>>>(dxh, nullptr, dch, nullptr, out, NL * NK,
                                                 nullptr, drn, dcn, scales, temp);
    }
}